// round 9
// baseline (speedup 1.0000x reference)
#include <cuda_runtime.h>
#include <math.h>

#define NS  1024
#define XD  128
#define HID 256

typedef unsigned long long ull;

// scratch (allocation-free rule: __device__ globals)
__device__ float g_pxT[HID * NS];   // [k][j] : px transposed
__device__ float g_pybT[HID * NS];  // [k][i] : (y@W1y + b1) transposed
__device__ float g_diag[NS];        // T1[i,i]
__device__ float g_e[NS];           // exp(lse_i - ln N)
__device__ int   g_ctr;             // last-block election (self-resetting)

// ---------------------------------------------------------------------------
// packed f32x2 helpers (sm_100+)
// ---------------------------------------------------------------------------
__device__ __forceinline__ ull dup2(float x) {
    ull r;
    asm("mov.b64 %0, {%1, %1};" : "=l"(r) : "f"(x));
    return r;
}

// acc2 += max(a2 + p2, 0) * w2   (elementwise on both packed lanes)
__device__ __forceinline__ void relu_fma2(ull& acc, ull a2, ull p2, ull w2) {
    asm("{\n\t"
        ".reg .b64 v;\n\t"
        ".reg .f32 lo, hi;\n\t"
        "add.rn.f32x2 v, %1, %2;\n\t"
        "mov.b64 {lo, hi}, v;\n\t"
        "max.f32 lo, lo, 0f00000000;\n\t"
        "max.f32 hi, hi, 0f00000000;\n\t"
        "mov.b64 v, {lo, hi};\n\t"
        "fma.rn.f32x2 %0, v, %3, %0;\n\t"
        "}"
        : "+l"(acc) : "l"(a2), "l"(p2), "l"(w2));
}

// ---------------------------------------------------------------------------
// GEMM: C_T[h][n] = sum_d A[n][d] * W1[z*128 + d][h]   (+ b1[h] when z==1)
// block tile 64h x 64n, 512 threads, thread tile 2h x 4n, smem-tiled.
// (R8 config)
// ---------------------------------------------------------------------------
__global__ __launch_bounds__(512) void gemm_kernel(
    const float* __restrict__ X, const float* __restrict__ Y,
    const float* __restrict__ W1, const float* __restrict__ b1)
{
    const int z  = blockIdx.z;
    const float* A = z ? Y : X;
    float* C = z ? g_pybT : g_pxT;
    const int h0 = blockIdx.y * 64;
    const int n0 = blockIdx.x * 64;
    const int t  = threadIdx.x;
    const int tx = t & 15;   // n quad index
    const int ty = t >> 4;   // h pair index (0..31)

    __shared__ float xs[64][68];  // [d][n] transposed, pad 68
    __shared__ float ws[64][64];  // [d][h]

    float acc[2][4];
#pragma unroll
    for (int i = 0; i < 2; i++)
#pragma unroll
        for (int j = 0; j < 4; j++) acc[i][j] = 0.f;

    for (int k0 = 0; k0 < XD; k0 += 64) {
        __syncthreads();
#pragma unroll
        for (int r = 0; r < 2; r++) {
            int f = t + 512 * r;          // 1024 float4s
            int n = f >> 4, d4 = (f & 15) * 4;
            float4 v = *(const float4*)&A[(n0 + n) * XD + k0 + d4];
            xs[d4 + 0][n] = v.x;
            xs[d4 + 1][n] = v.y;
            xs[d4 + 2][n] = v.z;
            xs[d4 + 3][n] = v.w;
        }
#pragma unroll
        for (int r = 0; r < 2; r++) {
            int f = t + 512 * r;
            int d = f >> 4, h4 = (f & 15) * 4;
            *(float4*)&ws[d][h4] =
                *(const float4*)&W1[(z * XD + k0 + d) * HID + h0 + h4];
        }
        __syncthreads();
#pragma unroll 8
        for (int d = 0; d < 64; d++) {
            float2 a = *(const float2*)&ws[d][ty * 2];
            float4 b = *(const float4*)&xs[d][tx * 4];
            const float av[2] = {a.x, a.y};
            const float bv[4] = {b.x, b.y, b.z, b.w};
#pragma unroll
            for (int i = 0; i < 2; i++)
#pragma unroll
                for (int j = 0; j < 4; j++)
                    acc[i][j] = fmaf(av[i], bv[j], acc[i][j]);
        }
    }

#pragma unroll
    for (int i = 0; i < 2; i++) {
        int h = h0 + ty * 2 + i;
        float bias = z ? b1[h] : 0.f;
        float4 o = make_float4(acc[i][0] + bias, acc[i][1] + bias,
                               acc[i][2] + bias, acc[i][3] + bias);
        *(float4*)&C[h * NS + n0 + tx * 4] = o;
    }
}

// ---------------------------------------------------------------------------
// Pair kernel: block = 8i x 1024j, 512 threads, K-SPLIT in 2 groups.
// Group g = t>>8 reduces k in [g*128, g*128+128) for j-quad jq = t&255:
// thread tile 8i x 4j = 16 packed f32x2 accumulators. px via LDG.128
// (unique addresses, read once per block), py/w2 dup'd broadcast LDS.
// Partials merged through reused smem; group 0 finishes lse; last block
// does the final scalar reduction (fused finish).
// ---------------------------------------------------------------------------
__global__ __launch_bounds__(512) void pair_kernel(
    const float* __restrict__ W2, const float* __restrict__ b2,
    float* __restrict__ out)
{
    __shared__ ull sm_py2[HID][8];    // dup'd pyb_T[k][ii] = {v,v} (16KB)
    __shared__ ull sm_w2[HID];        // dup'd W2 (2KB)
    __shared__ float red_m[8][8];     // [grp0 warp][ii]
    __shared__ float red_s[8][8];
    __shared__ int   s_last;
    __shared__ float sd[16], se[16];

    const int t   = threadIdx.x;
    const int jq  = t & 255;          // j-quad index: j = 4jq .. 4jq+3
    const int grp = t >> 8;           // k half
    const int i0  = blockIdx.x * 8;

    // one-time: duplicate pyb columns + W2 into packed smem
#pragma unroll
    for (int r = 0; r < 4; r++) {
        int f = t + 512 * r;          // 2048 entries
        int k = f >> 3, ii = f & 7;
        sm_py2[k][ii] = dup2(g_pybT[k * NS + i0 + ii]);
    }
    if (t < HID) sm_w2[t] = dup2(W2[t]);
    __syncthreads();

    ull acc2[16];                     // [ii][q] flat: ii*2+q
#pragma unroll
    for (int a = 0; a < 16; a++) acc2[a] = 0ull;

    const int kb = grp * (HID / 2);   // this group's k base
    // px rows as 16B chunks: chunk jq = packed pairs {4jq,4jq+1},{4jq+2,4jq+3}
    const ulonglong2* px4 = (const ulonglong2*)g_pxT;   // row k: NS/4 = 256

    ulonglong2 buf[2][2];
    buf[0][0] = px4[(kb + 0) * (NS / 4) + jq];
    buf[0][1] = px4[(kb + 1) * (NS / 4) + jq];

#pragma unroll 1
    for (int kl = 0; kl < HID / 2; kl += 2) {
        const int cur = (kl >> 1) & 1, nxt = cur ^ 1;
        const int knl = (kl + 2) & (HID / 2 - 1);   // wraps at end (harmless)
        buf[nxt][0] = px4[(kb + knl + 0) * (NS / 4) + jq];
        buf[nxt][1] = px4[(kb + knl + 1) * (NS / 4) + jq];

#pragma unroll
        for (int kk = 0; kk < 2; kk++) {
            const int k = kb + kl + kk;
            const ull w2v = sm_w2[k];
            const ulonglong2 p = buf[cur][kk];
            ulonglong2 a01 = *(const ulonglong2*)&sm_py2[k][0];
            ulonglong2 a23 = *(const ulonglong2*)&sm_py2[k][2];
            ulonglong2 a45 = *(const ulonglong2*)&sm_py2[k][4];
            ulonglong2 a67 = *(const ulonglong2*)&sm_py2[k][6];
            relu_fma2(acc2[0],  a01.x, p.x, w2v);
            relu_fma2(acc2[1],  a01.x, p.y, w2v);
            relu_fma2(acc2[2],  a01.y, p.x, w2v);
            relu_fma2(acc2[3],  a01.y, p.y, w2v);
            relu_fma2(acc2[4],  a23.x, p.x, w2v);
            relu_fma2(acc2[5],  a23.x, p.y, w2v);
            relu_fma2(acc2[6],  a23.y, p.x, w2v);
            relu_fma2(acc2[7],  a23.y, p.y, w2v);
            relu_fma2(acc2[8],  a45.x, p.x, w2v);
            relu_fma2(acc2[9],  a45.x, p.y, w2v);
            relu_fma2(acc2[10], a45.y, p.x, w2v);
            relu_fma2(acc2[11], a45.y, p.y, w2v);
            relu_fma2(acc2[12], a67.x, p.x, w2v);
            relu_fma2(acc2[13], a67.x, p.y, w2v);
            relu_fma2(acc2[14], a67.y, p.x, w2v);
            relu_fma2(acc2[15], a67.y, p.y, w2v);
        }
    }

    // ---- merge k-halves through reused sm_py2 (16KB): 2 rounds of 8 ----
    ull (*xch)[256] = (ull(*)[256])sm_py2;   // [8][256]
    union cvt { ull u; float2 f; };
    __syncthreads();                  // main loop done; sm_py2 reusable
#pragma unroll
    for (int rnd = 0; rnd < 2; rnd++) {
        if (grp == 1) {
#pragma unroll
            for (int a = 0; a < 8; a++) xch[a][jq] = acc2[rnd * 8 + a];
        }
        __syncthreads();
        if (grp == 0) {
#pragma unroll
            for (int a = 0; a < 8; a++) {
                cvt x, y; x.u = acc2[rnd * 8 + a]; y.u = xch[a][jq];
                x.f.x += y.f.x; x.f.y += y.f.y; acc2[rnd * 8 + a] = x.u;
            }
        }
        __syncthreads();
    }

    const int warp = t >> 5, lane = t & 31;

    // ---- epilogue (group 0 only: warps 0-7) ----
    if (grp == 0) {
        const float bm1 = b2[0] - 1.0f;
        float m[8], s[8];
#pragma unroll
        for (int ii = 0; ii < 8; ii++) {
            cvt c0, c1;
            c0.u = acc2[ii * 2];
            c1.u = acc2[ii * 2 + 1];
            float v[4] = {c0.f.x + bm1, c0.f.y + bm1,
                          c1.f.x + bm1, c1.f.y + bm1};
            const int ig = i0 + ii;
#pragma unroll
            for (int jj = 0; jj < 4; jj++)
                if (4 * jq + jj == ig) g_diag[ig] = v[jj];
            float mm = fmaxf(fmaxf(v[0], v[1]), fmaxf(v[2], v[3]));
            s[ii] = expf(v[0] - mm) + expf(v[1] - mm) +
                    expf(v[2] - mm) + expf(v[3] - mm);
            m[ii] = mm;
        }
#pragma unroll
        for (int off = 16; off > 0; off >>= 1) {
#pragma unroll
            for (int ii = 0; ii < 8; ii++) {
                float om = __shfl_xor_sync(0xffffffffu, m[ii], off);
                float os = __shfl_xor_sync(0xffffffffu, s[ii], off);
                float M  = fmaxf(m[ii], om);
                s[ii] = s[ii] * expf(m[ii] - M) + os * expf(om - M);
                m[ii] = M;
            }
        }
        if (lane == 0) {
#pragma unroll
            for (int ii = 0; ii < 8; ii++) {
                red_m[warp][ii] = m[ii];
                red_s[warp][ii] = s[ii];
            }
        }
    }
    __syncthreads();
    if (t < 8) {
        float M = red_m[0][t], S = red_s[0][t];
#pragma unroll
        for (int w = 1; w < 8; w++) {
            float om = red_m[w][t], os = red_s[w][t];
            float M2 = fmaxf(M, om);
            S = S * expf(M - M2) + os * expf(om - M2);
            M = M2;
        }
        float lse = M + logf(S);
        g_e[i0 + t] = expf(lse - logf((float)NS));
    }

    // ---- fused finish: last block reduces diag + e, writes the scalar ----
    __threadfence();
    __syncthreads();
    if (t == 0)
        s_last = (atomicAdd(&g_ctr, 1) == (int)gridDim.x - 1);
    __syncthreads();
    if (!s_last) return;
    __threadfence();                  // acquire other blocks' writes

    float d = g_diag[t] + g_diag[t + 512];
    float e = g_e[t]    + g_e[t + 512];
#pragma unroll
    for (int off = 16; off > 0; off >>= 1) {
        d += __shfl_xor_sync(0xffffffffu, d, off);
        e += __shfl_xor_sync(0xffffffffu, e, off);
    }
    if (lane == 0) { sd[warp] = d; se[warp] = e; }
    __syncthreads();
    if (t < 16) {
        float dd = sd[t], ee = se[t];
#pragma unroll
        for (int off = 8; off > 0; off >>= 1) {
            dd += __shfl_xor_sync(0xffffu, dd, off);
            ee += __shfl_xor_sync(0xffffu, ee, off);
        }
        if (t == 0) {
            out[0] = dd * (1.0f / NS) + 1.0f - ee * (1.0f / NS);
            g_ctr = 0;                // self-reset for graph replay
        }
    }
}

// ---------------------------------------------------------------------------
extern "C" void kernel_launch(void* const* d_in, const int* in_sizes, int n_in,
                              void* d_out, int out_size)
{
    const float* x  = (const float*)d_in[0];
    const float* y  = (const float*)d_in[1];
    const float* W1 = (const float*)d_in[2];
    const float* b1 = (const float*)d_in[3];
    const float* W2 = (const float*)d_in[4];
    const float* b2 = (const float*)d_in[5];

    dim3 gg(NS / 64, HID / 64, 2);          // 16 x 4 x 2 = 128 blocks
    gemm_kernel<<<gg, 512>>>(x, y, W1, b1);
    pair_kernel<<<NS / 8, 512>>>(W2, b2, (float*)d_out);  // 128 blocks
}

// round 11
// speedup vs baseline: 1.1137x; 1.1137x over previous
#include <cuda_runtime.h>
#include <math.h>

#define NS  1024
#define XD  128
#define HID 256
#define RPB 7          // i-rows per pair block
#define NBLK 147       // ceil(1024/7) = 147 blocks -> one per SM

typedef unsigned long long ull;

// scratch (allocation-free rule: __device__ globals)
__device__ float g_pxT[HID * NS];   // [k][j] : px transposed
__device__ float g_pybT[HID * NS];  // [k][i] : (y@W1y + b1) transposed
__device__ float g_diag[NS];        // T1[i,i]
__device__ float g_e[NS];           // exp(lse_i - ln N)
__device__ int   g_ctr;             // last-block election (self-resetting)

// ---------------------------------------------------------------------------
// packed f32x2 helpers (sm_100+)
// ---------------------------------------------------------------------------
__device__ __forceinline__ ull dup2(float x) {
    ull r;
    asm("mov.b64 %0, {%1, %1};" : "=l"(r) : "f"(x));
    return r;
}

// acc2 += max(a2 + p2, 0) * w2   (ADD2 + 2x scalar MAX + FMA2; proven R8)
__device__ __forceinline__ void relu_fma2(ull& acc, ull a2, ull p2, ull w2) {
    asm("{\n\t"
        ".reg .b64 v;\n\t"
        ".reg .f32 lo, hi;\n\t"
        "add.rn.f32x2 v, %1, %2;\n\t"
        "mov.b64 {lo, hi}, v;\n\t"
        "max.f32 lo, lo, 0f00000000;\n\t"
        "max.f32 hi, hi, 0f00000000;\n\t"
        "mov.b64 v, {lo, hi};\n\t"
        "fma.rn.f32x2 %0, v, %3, %0;\n\t"
        "}"
        : "+l"(acc) : "l"(a2), "l"(p2), "l"(w2));
}

// ---------------------------------------------------------------------------
// GEMM: C_T[h][n] = sum_d A[n][d] * W1[z*128 + d][h]   (+ b1[h] when z==1)
// block tile 64h x 64n, 512 threads, thread tile 2h x 4n, smem-tiled.
// (R8 config)
// ---------------------------------------------------------------------------
__global__ __launch_bounds__(512) void gemm_kernel(
    const float* __restrict__ X, const float* __restrict__ Y,
    const float* __restrict__ W1, const float* __restrict__ b1)
{
    const int z  = blockIdx.z;
    const float* A = z ? Y : X;
    float* C = z ? g_pybT : g_pxT;
    const int h0 = blockIdx.y * 64;
    const int n0 = blockIdx.x * 64;
    const int t  = threadIdx.x;
    const int tx = t & 15;   // n quad index
    const int ty = t >> 4;   // h pair index (0..31)

    __shared__ float xs[64][68];  // [d][n] transposed, pad 68
    __shared__ float ws[64][64];  // [d][h]

    float acc[2][4];
#pragma unroll
    for (int i = 0; i < 2; i++)
#pragma unroll
        for (int j = 0; j < 4; j++) acc[i][j] = 0.f;

    for (int k0 = 0; k0 < XD; k0 += 64) {
        __syncthreads();
#pragma unroll
        for (int r = 0; r < 2; r++) {
            int f = t + 512 * r;          // 1024 float4s
            int n = f >> 4, d4 = (f & 15) * 4;
            float4 v = *(const float4*)&A[(n0 + n) * XD + k0 + d4];
            xs[d4 + 0][n] = v.x;
            xs[d4 + 1][n] = v.y;
            xs[d4 + 2][n] = v.z;
            xs[d4 + 3][n] = v.w;
        }
#pragma unroll
        for (int r = 0; r < 2; r++) {
            int f = t + 512 * r;
            int d = f >> 4, h4 = (f & 15) * 4;
            *(float4*)&ws[d][h4] =
                *(const float4*)&W1[(z * XD + k0 + d) * HID + h0 + h4];
        }
        __syncthreads();
#pragma unroll 8
        for (int d = 0; d < 64; d++) {
            float2 a = *(const float2*)&ws[d][ty * 2];
            float4 b = *(const float4*)&xs[d][tx * 4];
            const float av[2] = {a.x, a.y};
            const float bv[4] = {b.x, b.y, b.z, b.w};
#pragma unroll
            for (int i = 0; i < 2; i++)
#pragma unroll
                for (int j = 0; j < 4; j++)
                    acc[i][j] = fmaf(av[i], bv[j], acc[i][j]);
        }
    }

#pragma unroll
    for (int i = 0; i < 2; i++) {
        int h = h0 + ty * 2 + i;
        float bias = z ? b1[h] : 0.f;
        float4 o = make_float4(acc[i][0] + bias, acc[i][1] + bias,
                               acc[i][2] + bias, acc[i][3] + bias);
        *(float4*)&C[h * NS + n0 + tx * 4] = o;
    }
}

// ---------------------------------------------------------------------------
// Pair kernel: 147 blocks (one per SM) x 7 i-rows x 1024 j, 1024 threads.
// K-SPLIT: group g = t>>9 reduces k in [g*128, g*128+128) for jp = t&511
// (7i x 2j accumulators). No px LDG duplication; 8 warps/SMSP; batched w2.
// Partials merged through reused smem; group 0 finishes lse; last block
// does the final scalar reduction.
// ---------------------------------------------------------------------------
__global__ __launch_bounds__(1024) void pair_kernel(
    const float* __restrict__ W2, const float* __restrict__ b2,
    float* __restrict__ out)
{
    __shared__ ull sm_py2[HID][8];    // dup'd pyb_T[k][ii] (ii 7 = pad) 16KB
    __shared__ ull sm_w2[HID];        // dup'd W2 (2KB)
    __shared__ float red_m[16][RPB];  // [grp0 warp][ii]
    __shared__ float red_s[16][RPB];
    __shared__ int   s_last;
    __shared__ float sd[32], se[32];

    const int t   = threadIdx.x;
    const int jp  = t & 511;          // j-pair index: j = 2jp, 2jp+1
    const int grp = t >> 9;           // k half
    const int i0  = blockIdx.x * RPB;

    // one-time: duplicate pyb columns + W2 into packed smem (guarded tail)
#pragma unroll
    for (int r = 0; r < 2; r++) {
        int f = t + 1024 * r;         // 2048 entries
        int k = f >> 3, ii = f & 7;
        int idx = i0 + ii;
        float v = (ii < RPB && idx < NS) ? g_pybT[k * NS + idx] : 0.f;
        sm_py2[k][ii] = dup2(v);
    }
    if (t < HID) sm_w2[t] = dup2(W2[t]);
    __syncthreads();

    ull acc2[RPB];
#pragma unroll
    for (int ii = 0; ii < RPB; ii++) acc2[ii] = 0ull;

    const int kb = grp * (HID / 2);       // this group's k base
    const ull* pxu = (const ull*)g_pxT;   // row k: NS/2 = 512 packed pairs

    ull buf[2][4];
#pragma unroll
    for (int kk = 0; kk < 4; kk++)
        buf[0][kk] = pxu[(kb + kk) * (NS / 2) + jp];

#pragma unroll 1
    for (int kl = 0; kl < HID / 2; kl += 4) {
        const int cur = (kl >> 2) & 1, nxt = cur ^ 1;
        const int knl = (kl + 4) & (HID / 2 - 1);   // wraps at end (harmless)
#pragma unroll
        for (int kk = 0; kk < 4; kk++)
            buf[nxt][kk] = pxu[(kb + knl + kk) * (NS / 2) + jp];

        // batched w2 for this k-quad: 2 x LDS.128
        ulonglong2 w01 = *(const ulonglong2*)&sm_w2[kb + kl];
        ulonglong2 w23 = *(const ulonglong2*)&sm_w2[kb + kl + 2];
        const ull wv[4] = {w01.x, w01.y, w23.x, w23.y};

#pragma unroll
        for (int kk = 0; kk < 4; kk++) {
            const int k = kb + kl + kk;
            const ull p = buf[cur][kk];
            ulonglong2 a01 = *(const ulonglong2*)&sm_py2[k][0];
            ulonglong2 a23 = *(const ulonglong2*)&sm_py2[k][2];
            ulonglong2 a45 = *(const ulonglong2*)&sm_py2[k][4];
            ull        a6  = sm_py2[k][6];
            relu_fma2(acc2[0], a01.x, p, wv[kk]);
            relu_fma2(acc2[1], a01.y, p, wv[kk]);
            relu_fma2(acc2[2], a23.x, p, wv[kk]);
            relu_fma2(acc2[3], a23.y, p, wv[kk]);
            relu_fma2(acc2[4], a45.x, p, wv[kk]);
            relu_fma2(acc2[5], a45.y, p, wv[kk]);
            relu_fma2(acc2[6], a6,    p, wv[kk]);
        }
    }

    // ---- merge k-halves: reuse sm_py2 (16KB) as exchange, rounds of 4+3 ----
    ull (*xch)[512] = (ull(*)[512])sm_py2;   // [4][512]
    union cvt { ull u; float2 f; };
    __syncthreads();                  // main loop done; sm_py2 reusable
    if (grp == 1) {
#pragma unroll
        for (int ii = 0; ii < 4; ii++) xch[ii][jp] = acc2[ii];
    }
    __syncthreads();
    if (grp == 0) {
#pragma unroll
        for (int ii = 0; ii < 4; ii++) {
            cvt a, b; a.u = acc2[ii]; b.u = xch[ii][jp];
            a.f.x += b.f.x; a.f.y += b.f.y; acc2[ii] = a.u;
        }
    }
    __syncthreads();
    if (grp == 1) {
#pragma unroll
        for (int ii = 0; ii < 3; ii++) xch[ii][jp] = acc2[ii + 4];
    }
    __syncthreads();
    if (grp == 0) {
#pragma unroll
        for (int ii = 0; ii < 3; ii++) {
            cvt a, b; a.u = acc2[ii + 4]; b.u = xch[ii][jp];
            a.f.x += b.f.x; a.f.y += b.f.y; acc2[ii + 4] = a.u;
        }
    }

    const int warp = t >> 5, lane = t & 31;

    // ---- epilogue (group 0 only; warp-uniform branch) ----
    if (grp == 0) {
        const float bm1 = b2[0] - 1.0f;
        float m[RPB], s[RPB];
#pragma unroll
        for (int ii = 0; ii < RPB; ii++) {
            cvt c; c.u = acc2[ii];
            float v0 = c.f.x + bm1;
            float v1 = c.f.y + bm1;
            const int ig = i0 + ii;   // ig >= NS never matches 2jp <= 1023
            if (2 * jp == ig)     g_diag[ig] = v0;
            if (2 * jp + 1 == ig) g_diag[ig] = v1;
            float mm = fmaxf(v0, v1);
            s[ii] = expf(v0 - mm) + expf(v1 - mm);
            m[ii] = mm;
        }
#pragma unroll
        for (int off = 16; off > 0; off >>= 1) {
#pragma unroll
            for (int ii = 0; ii < RPB; ii++) {
                float om = __shfl_xor_sync(0xffffffffu, m[ii], off);
                float os = __shfl_xor_sync(0xffffffffu, s[ii], off);
                float M  = fmaxf(m[ii], om);
                s[ii] = s[ii] * expf(m[ii] - M) + os * expf(om - M);
                m[ii] = M;
            }
        }
        if (lane == 0) {
#pragma unroll
            for (int ii = 0; ii < RPB; ii++) {
                red_m[warp][ii] = m[ii];
                red_s[warp][ii] = s[ii];
            }
        }
    }
    __syncthreads();
    if (t < RPB && i0 + t < NS) {
        float M = red_m[0][t], S = red_s[0][t];
#pragma unroll
        for (int w = 1; w < 16; w++) {
            float om = red_m[w][t], os = red_s[w][t];
            float M2 = fmaxf(M, om);
            S = S * expf(M - M2) + os * expf(om - M2);
            M = M2;
        }
        float lse = M + logf(S);
        g_e[i0 + t] = expf(lse - logf((float)NS));
    }

    // ---- fused finish: last block reduces diag + e, writes the scalar ----
    __threadfence();
    __syncthreads();
    if (t == 0)
        s_last = (atomicAdd(&g_ctr, 1) == (int)gridDim.x - 1);
    __syncthreads();
    if (!s_last) return;
    __threadfence();                  // acquire other blocks' writes

    float d = g_diag[t];
    float e = g_e[t];
#pragma unroll
    for (int off = 16; off > 0; off >>= 1) {
        d += __shfl_xor_sync(0xffffffffu, d, off);
        e += __shfl_xor_sync(0xffffffffu, e, off);
    }
    if (lane == 0) { sd[warp] = d; se[warp] = e; }
    __syncthreads();
    if (t < 32) {
        float dd = sd[t], ee = se[t];
#pragma unroll
        for (int off = 16; off > 0; off >>= 1) {
            dd += __shfl_xor_sync(0xffffffffu, dd, off);
            ee += __shfl_xor_sync(0xffffffffu, ee, off);
        }
        if (t == 0) {
            out[0] = dd * (1.0f / NS) + 1.0f - ee * (1.0f / NS);
            g_ctr = 0;                // self-reset for graph replay
        }
    }
}

// ---------------------------------------------------------------------------
extern "C" void kernel_launch(void* const* d_in, const int* in_sizes, int n_in,
                              void* d_out, int out_size)
{
    const float* x  = (const float*)d_in[0];
    const float* y  = (const float*)d_in[1];
    const float* W1 = (const float*)d_in[2];
    const float* b1 = (const float*)d_in[3];
    const float* W2 = (const float*)d_in[4];
    const float* b2 = (const float*)d_in[5];

    dim3 gg(NS / 64, HID / 64, 2);          // 16 x 4 x 2 = 128 blocks
    gemm_kernel<<<gg, 512>>>(x, y, W1, b1);
    pair_kernel<<<NBLK, 1024>>>(W2, b2, (float*)d_out);  // 147 blocks
}